// round 16
// baseline (speedup 1.0000x reference)
#include <cuda_runtime.h>
#include <mma.h>
using namespace nvcuda;

#define TSCALE 256
#define NS 32
#define NW 8
#define NTW 65536
#define JTOT 4096
#define DIMX 512
#define H1 256
#define H3 512
#define H2 128
#define UCOLS 16384

// ---------------- scratch ----------------
__device__ float d_hT[2 * TSCALE * H1];
__device__ float d_WT[H1 * UCOLS];
__device__ float d_U[(size_t)512 * UCOLS];
__device__ int   d_midx[NTW * 8];
__device__ float d_mval[NTW * 8];
__device__ float d_Y[(size_t)JTOT * H3];        // stage2 output (bias included)
__device__ float d_F[H2 * JTOT];                // raw r2d output
__device__ float d_HT2[2][H2 * JTOT];           // raw head conv outputs
__device__ float2 d_p3[2 * 32 * 256];           // GN3 partials
__device__ float2 d_p2[2 * 32 * 64];            // GN2 partials (64 j-tile chunks)
__device__ float2 d_ph[2][2 * 32 * 8];          // GN-heads partials

// ---------------- packed f32x2 FMA ----------------
__device__ __forceinline__ void ffma2(float& d0, float& d1,
                                      float a0, float a1,
                                      float b0, float b1) {
    asm("{\n\t"
        ".reg .b64 ra, rb, rc;\n\t"
        "mov.b64 ra, {%2, %3};\n\t"
        "mov.b64 rb, {%4, %5};\n\t"
        "mov.b64 rc, {%0, %1};\n\t"
        "fma.rn.f32x2 rc, ra, rb, rc;\n\t"
        "mov.b64 {%0, %1}, rc;\n\t"
        "}"
        : "+f"(d0), "+f"(d1)
        : "f"(a0), "f"(a1), "f"(b0), "f"(b1));
}

// ---------------- deterministic block tree-reduce of (sum,sumsq) ----------------
__device__ __forceinline__ float2 block_reduce2(float s, float sq) {
    __shared__ float sh[512];
    int tid = threadIdx.x;
    __syncthreads();
    sh[tid] = s; sh[256 + tid] = sq;
    __syncthreads();
    for (int st = 128; st > 0; st >>= 1) {
        if (tid < st) { sh[tid] += sh[tid + st]; sh[256 + tid] += sh[256 + tid + st]; }
        __syncthreads();
    }
    return make_float2(sh[0], sh[256]);
}

// 8-lane shuffle reduce of float2
__device__ __forceinline__ float2 shfl8_reduce2(float2 v) {
    v.x += __shfl_xor_sync(~0u, v.x, 1); v.y += __shfl_xor_sync(~0u, v.y, 1);
    v.x += __shfl_xor_sync(~0u, v.x, 2); v.y += __shfl_xor_sync(~0u, v.y, 2);
    v.x += __shfl_xor_sync(~0u, v.x, 4); v.y += __shfl_xor_sync(~0u, v.y, 4);
    return v;
}

// full-warp shuffle reduce of float2
__device__ __forceinline__ float2 shfl32_reduce2(float2 v) {
    v.x += __shfl_xor_sync(~0u, v.x, 1);  v.y += __shfl_xor_sync(~0u, v.y, 1);
    v.x += __shfl_xor_sync(~0u, v.x, 2);  v.y += __shfl_xor_sync(~0u, v.y, 2);
    v.x += __shfl_xor_sync(~0u, v.x, 4);  v.y += __shfl_xor_sync(~0u, v.y, 4);
    v.x += __shfl_xor_sync(~0u, v.x, 8);  v.y += __shfl_xor_sync(~0u, v.y, 8);
    v.x += __shfl_xor_sync(~0u, v.x, 16); v.y += __shfl_xor_sync(~0u, v.y, 16);
    return v;
}

// ---------------- prep: conv1+GN1 | W transpose | mask scan (grid-split) ----------------
__global__ void __launch_bounds__(256) prep_kernel(const float* __restrict__ x,
                                                   const float* __restrict__ cw,
                                                   const float* __restrict__ cbias,
                                                   const float* __restrict__ gamma,
                                                   const float* __restrict__ beta,
                                                   const float* __restrict__ rw,
                                                   const float* __restrict__ mask) {
    int bid = blockIdx.x;
    if (bid < 64) {
        int g = bid & 31, b = bid >> 5;
        int c0 = g * 8;
        int t = threadIdx.x;
        __shared__ float xs[8][TSCALE + 2];
        __shared__ float ws[8][8][3];
        float acc[8];
#pragma unroll
        for (int u = 0; u < 8; u++) acc[u] = cbias[c0 + u];
        for (int i0 = 0; i0 < DIMX; i0 += 8) {
#pragma unroll
            for (int r = 0; r < 8; r++)
                xs[r][t + 1] = x[(b * DIMX + i0 + r) * TSCALE + t];
            if (t < 8) { xs[t][0] = 0.f; xs[t][TSCALE + 1] = 0.f; }
            if (t < 192) {
                int u = t / 24, rem = t % 24, r = rem / 3, k = rem % 3;
                ws[u][r][k] = cw[(c0 + u) * (DIMX * 3) + (i0 + r) * 3 + k];
            }
            __syncthreads();
#pragma unroll
            for (int r = 0; r < 8; r++) {
                float xm = xs[r][t], x0 = xs[r][t + 1], xp = xs[r][t + 2];
#pragma unroll
                for (int u = 0; u < 8; u++)
                    acc[u] += xm * ws[u][r][0] + x0 * ws[u][r][1] + xp * ws[u][r][2];
            }
            __syncthreads();
        }
        float s = 0.f, sq = 0.f;
#pragma unroll
        for (int u = 0; u < 8; u++) { s += acc[u]; sq += acc[u] * acc[u]; }
        float2 tot = block_reduce2(s, sq);
        float mean = tot.x / 2048.f;
        float var  = tot.y / 2048.f - mean * mean;
        float inv  = rsqrtf(var + 1e-5f);
        float v[8];
#pragma unroll
        for (int u = 0; u < 8; u++)
            v[u] = fmaxf((acc[u] - mean) * inv * gamma[c0 + u] + beta[c0 + u], 0.f);
        float* dst = &d_hT[(b * 256 + t) * 256 + c0];
        *(float4*)dst       = make_float4(v[0], v[1], v[2], v[3]);
        *(float4*)(dst + 4) = make_float4(v[4], v[5], v[6], v[7]);
    } else if (bid < 64 + 4096) {
        int q = bid - 64;
        int c  = q & 255;
        int o0 = (q >> 8) * 32;
        __shared__ float tile[32][33];
        int tid = threadIdx.x;
#pragma unroll
        for (int l = 0; l < 4; l++) {
            int e = tid + l * 256;
            int i = e >> 5, n = e & 31;
            tile[i][n] = rw[(size_t)(o0 + i) * 8192 + c * 32 + n];
        }
        __syncthreads();
#pragma unroll
        for (int l = 0; l < 4; l++) {
            int e = tid + l * 256;
            int n = e >> 5, i = e & 31;
            d_WT[(size_t)c * UCOLS + n * 512 + o0 + i] = tile[i][n];
        }
    } else {
        int j = (bid - 64 - 4096) * 256 + threadIdx.x;
        int n = j >> 11, t = (j >> 3) & 255, w = j & 7;
        const float WS[8] = {5.f, 10.f, 20.f, 40.f, 80.f, 160.f, 240.f, 320.f};
        float ws = WS[w];
        float dd = ws * 0.5f;
        float step = ws / 95.f;
        float s0 = (float)t - dd + step * (float)(3 * n);
        float s2 = (float)t - dd + step * (float)(3 * n + 2);
        int lo = max(0, (int)floorf(s0) - 1);
        int hi = min(255, (int)ceilf(s2) + 1);
        int idxs[8]; float vals[8];
        int cnt = 0;
        for (int tin = lo; tin <= hi; tin++) {
            float v = mask[(size_t)tin * NTW + j];
            if (v != 0.f && cnt < 8) { idxs[cnt] = tin; vals[cnt] = v; cnt++; }
        }
#pragma unroll
        for (int s = 0; s < 8; s++) {
            d_midx[j * 8 + s] = (s < cnt) ? idxs[s] : 0;
            d_mval[j * 8 + s] = (s < cnt) ? vals[s] : 0.f;
        }
    }
}

// ---------------- U-GEMM ----------------
#define BM 128
#define BN 128
#define BK 32
#define STAGES 2
#define AS_STRIDE (BM * 36)
#define BS_STRIDE (BK * 132)
#define NKT (H1 / BK)

__device__ __forceinline__ void cp16(void* sdst, const void* gsrc) {
    unsigned saddr = (unsigned)__cvta_generic_to_shared(sdst);
    asm volatile("cp.async.cg.shared.global [%0], [%1], 16;\n"
                 :: "r"(saddr), "l"(gsrc));
}

__global__ void __launch_bounds__(256, 2) u_gemm_kernel() {
    extern __shared__ float smem[];
    float* As = smem;
    float* Bs = smem + STAGES * AS_STRIDE;
    int m0 = blockIdx.x * BM;
    int n0 = blockIdx.y * BN;
    int tid = threadIdx.x;
    int warp = tid >> 5;
    int wm = warp & 1, wn = warp >> 1;

    wmma::fragment<wmma::accumulator, 16, 16, 8, float> acc[4][2];
#pragma unroll
    for (int i = 0; i < 4; i++)
#pragma unroll
        for (int j = 0; j < 2; j++) wmma::fill_fragment(acc[i][j], 0.f);

    auto issue = [&](int s, int kt) {
        int k0 = kt * BK;
        float* as = As + s * AS_STRIDE;
#pragma unroll
        for (int l = 0; l < 4; l++) {
            int q = tid + l * 256;
            int r = q >> 3, c = (q & 7) << 2;
            cp16(as + r * 36 + c, d_hT + (size_t)(m0 + r) * H1 + k0 + c);
        }
        float* bs = Bs + s * BS_STRIDE;
#pragma unroll
        for (int l = 0; l < 4; l++) {
            int q = tid + l * 256;
            int r = q >> 5, c = (q & 31) << 2;
            cp16(bs + r * 132 + c, d_WT + (size_t)(k0 + r) * UCOLS + n0 + c);
        }
        asm volatile("cp.async.commit_group;\n");
    };

    issue(0, 0);
    for (int kt = 0; kt < NKT; kt++) {
        if (kt + 1 < NKT) {
            issue((kt + 1) & 1, kt + 1);
            asm volatile("cp.async.wait_group 1;\n");
        } else {
            asm volatile("cp.async.wait_group 0;\n");
        }
        __syncthreads();
        int s = kt & 1;
        float* as = As + s * AS_STRIDE;
        float* bs = Bs + s * BS_STRIDE;
#pragma unroll
        for (int kk = 0; kk < BK; kk += 8) {
            wmma::fragment<wmma::matrix_a, 16, 16, 8, wmma::precision::tf32, wmma::row_major> af[4];
            wmma::fragment<wmma::matrix_b, 16, 16, 8, wmma::precision::tf32, wmma::row_major> bf[2];
#pragma unroll
            for (int i = 0; i < 4; i++)
                wmma::load_matrix_sync(af[i], as + (wm * 64 + i * 16) * 36 + kk, 36);
#pragma unroll
            for (int j = 0; j < 2; j++)
                wmma::load_matrix_sync(bf[j], bs + kk * 132 + wn * 32 + j * 16, 132);
#pragma unroll
            for (int i = 0; i < 4; i++)
#pragma unroll
                for (int j = 0; j < 2; j++)
                    wmma::mma_sync(acc[i][j], af[i], bf[j], acc[i][j]);
        }
        __syncthreads();
    }
#pragma unroll
    for (int i = 0; i < 4; i++)
#pragma unroll
        for (int j = 0; j < 2; j++)
            wmma::store_matrix_sync(d_U + (size_t)(m0 + wm * 64 + i * 16) * UCOLS + n0 + wn * 32 + j * 16,
                                    acc[i][j], UCOLS, wmma::mem_row_major);
}

// ---------------- stage2 (+ bias + fused GN3 partials) ----------------
__global__ void __launch_bounds__(256) stage2_kernel(const float* __restrict__ bias3) {
    int t0 = blockIdx.x * 8;
    int w  = blockIdx.y;
    int b  = blockIdx.z;
    int tid  = threadIdx.x;
    int lane = tid & 31;
    int wid  = tid >> 5;

    __shared__ int   sidx[NS][8][8];
    __shared__ float sval[NS][8][8];
#pragma unroll
    for (int l = 0; l < 8; l++) {
        int e = tid + l * 256;
        int n = e >> 6, rem = e & 63;
        int tl = rem >> 3, s = rem & 7;
        int j = n * 2048 + (t0 + tl) * 8 + w;
        sidx[n][tl][s] = d_midx[j * 8 + s];
        sval[n][tl][s] = d_mval[j * 8 + s];
    }
    __syncthreads();

    float4 acc[4];
#pragma unroll
    for (int p = 0; p < 4; p++) acc[p] = make_float4(0.f, 0.f, 0.f, 0.f);

    const float4* __restrict__ U4 = (const float4*)d_U;
    for (int n = 0; n < NS; n++) {
#pragma unroll
        for (int s = 0; s < 6; s++) {
            float v = sval[n][wid][s];
            if (v != 0.f) {
                int tin = sidx[n][wid][s];
                size_t base4 = (size_t)(b * 256 + tin) * 4096 + n * 128 + lane;
#pragma unroll
                for (int p = 0; p < 4; p++) {
                    float4 u = U4[base4 + p * 32];
                    ffma2(acc[p].x, acc[p].y, v, v, u.x, u.y);
                    ffma2(acc[p].z, acc[p].w, v, v, u.z, u.w);
                }
            }
        }
    }
    float2 gsum[4];
#pragma unroll
    for (int p = 0; p < 4; p++) {
        float4 bb = ((const float4*)bias3)[p * 32 + lane];
        acc[p].x += bb.x; acc[p].y += bb.y; acc[p].z += bb.z; acc[p].w += bb.w;
        float s  = acc[p].x + acc[p].y + acc[p].z + acc[p].w;
        float sq = acc[p].x * acc[p].x + acc[p].y * acc[p].y
                 + acc[p].z * acc[p].z + acc[p].w * acc[p].w;
        s  += __shfl_xor_sync(~0u, s, 1);  sq += __shfl_xor_sync(~0u, sq, 1);
        s  += __shfl_xor_sync(~0u, s, 2);  sq += __shfl_xor_sync(~0u, sq, 2);
        gsum[p] = make_float2(s, sq);
    }
    float4* Y4 = (float4*)d_Y;
    int t = t0 + wid;
    size_t ob = (size_t)(b * 2048 + t * 8 + w) * 128 + lane;
#pragma unroll
    for (int p = 0; p < 4; p++) Y4[ob + p * 32] = acc[p];

    __shared__ float2 sred[8][32];
    if ((lane & 3) == 0) {
#pragma unroll
        for (int p = 0; p < 4; p++)
            sred[wid][p * 8 + (lane >> 2)] = gsum[p];
    }
    __syncthreads();
    if (tid < 32) {
        float2 tot = make_float2(0.f, 0.f);
#pragma unroll
        for (int ww = 0; ww < 8; ww++) { tot.x += sred[ww][tid].x; tot.y += sred[ww][tid].y; }
        int chunk = blockIdx.x * 8 + w;
        d_p3[(b * 32 + tid) * 256 + chunk] = tot;
    }
}

// ---------------- r2d v3: h-tile 32, 512 blocks (combine3 + apply + GN2 partials) ------
// grid (128 j-tiles of 32, 4 h-tiles of 32); threads 256 = (jl 32, warp hg 8 of 4 h)
__global__ void __launch_bounds__(256) r2d_kernel(const float* __restrict__ w2,
                                                  const float* __restrict__ b2,
                                                  const float* __restrict__ gamma3,
                                                  const float* __restrict__ beta3) {
    int bx = blockIdx.x;
    int j0 = bx * 32;
    int b  = bx >> 6;
    int h0 = blockIdx.y * 32;
    int tid = threadIdx.x;
    int jl = tid & 31, hg = tid >> 5;

    __shared__ float sA[512], sB[512];
    __shared__ float ytile[32][65];
    __shared__ __align__(16) float wst[64][36];

    // combine3 redundantly
    {
        int g = tid >> 3, sl = tid & 7;
        float2 part = make_float2(0.f, 0.f);
        const float2* pp = &d_p3[(b * 32 + g) * 256 + sl * 32];
#pragma unroll 8
        for (int k = 0; k < 32; k++) { float2 p = pp[k]; part.x += p.x; part.y += p.y; }
        float2 tot = shfl8_reduce2(part);
        float mean = tot.x / 32768.f;
        float var  = tot.y / 32768.f - mean * mean;
        float inv  = rsqrtf(var + 1e-5f);
#pragma unroll
        for (int q = 0; q < 2; q++) {
            int o = g * 16 + sl * 2 + q;
            float A = inv * gamma3[o];
            sA[o] = A;
            sB[o] = beta3[o] - mean * A;
        }
    }

    float acc[4];
#pragma unroll
    for (int u = 0; u < 4; u++) acc[u] = b2[h0 + hg * 4 + u];
    __syncthreads();

    const float4* __restrict__ Y4 = (const float4*)d_Y;
    for (int oc = 0; oc < 512; oc += 64) {
        __syncthreads();
        // ytile: 32 j x 64 o, GN3+relu applied; coalesced float4 reads
#pragma unroll
        for (int l = 0; l < 2; l++) {
            int e = tid + l * 256;
            int row = e >> 4, o4 = e & 15;
            float4 y = Y4[(size_t)(j0 + row) * 128 + (oc >> 2) + o4];
            int ob = oc + o4 * 4;
            ytile[row][o4 * 4 + 0] = fmaxf(y.x * sA[ob + 0] + sB[ob + 0], 0.f);
            ytile[row][o4 * 4 + 1] = fmaxf(y.y * sA[ob + 1] + sB[ob + 1], 0.f);
            ytile[row][o4 * 4 + 2] = fmaxf(y.z * sA[ob + 2] + sB[ob + 2], 0.f);
            ytile[row][o4 * 4 + 3] = fmaxf(y.w * sA[ob + 3] + sB[ob + 3], 0.f);
        }
        // wst: 64 o x 32 h
#pragma unroll
        for (int l = 0; l < 8; l++) {
            int e = tid + l * 256;
            int h = e >> 6, o = e & 63;
            wst[o][h] = w2[(size_t)(h0 + h) * 512 + oc + o];
        }
        __syncthreads();
#pragma unroll 4
        for (int o = 0; o < 64; o++) {
            float yv = ytile[jl][o];
            float4 w0 = *(const float4*)&wst[o][hg * 4];
            ffma2(acc[0], acc[1], yv, yv, w0.x, w0.y);
            ffma2(acc[2], acc[3], yv, yv, w0.z, w0.w);
        }
    }
    int j = j0 + jl;
#pragma unroll
    for (int u = 0; u < 4; u++)
        d_F[(h0 + hg * 4 + u) * JTOT + j] = acc[u];

    // GN2 partials: warp hg covers exactly one group of 4 h; lanes = j
    {
        float s  = acc[0] + acc[1] + acc[2] + acc[3];
        float sq = acc[0] * acc[0] + acc[1] * acc[1] + acc[2] * acc[2] + acc[3] * acc[3];
        float2 tot = shfl32_reduce2(make_float2(s, sq));
        if (jl == 0) {
            int g = (h0 >> 2) + hg;
            d_p2[(b * 32 + g) * 64 + (bx & 63)] = tot;
        }
    }
}

// ---------------- heads conv3x3 (combine2 + GN2 apply + GN-heads partials fused) ------
__global__ void __launch_bounds__(256) head_conv3_kernel(const float* __restrict__ ws_,
                                                         const float* __restrict__ bs_,
                                                         const float* __restrict__ we_,
                                                         const float* __restrict__ be_,
                                                         const float* __restrict__ g2,
                                                         const float* __restrict__ bb2) {
    int t0 = blockIdx.x * 32;
    int o0 = blockIdx.y * 16;
    int head = blockIdx.z >> 1, b = blockIdx.z & 1;
    const float* w    = head ? we_ : ws_;
    const float* bias = head ? be_ : bs_;
    int tid = threadIdx.x;
    int tl = tid >> 3, wq = tid & 7;
    __shared__ float fs[4][34][10];
    __shared__ __align__(16) float ws[4][9][16];
    __shared__ float sA2[128], sB2[128];
    {
        int g = tid >> 3, sl = tid & 7;
        float2 part = make_float2(0.f, 0.f);
        const float2* pp = &d_p2[(b * 32 + g) * 64 + sl * 8];
#pragma unroll 8
        for (int k = 0; k < 8; k++) { float2 p = pp[k]; part.x += p.x; part.y += p.y; }
        float2 tot = shfl8_reduce2(part);
        float mean = tot.x / 8192.f;
        float var  = tot.y / 8192.f - mean * mean;
        float inv  = rsqrtf(var + 1e-5f);
        if (sl < 4) {
            int ch = g * 4 + sl;
            float A = inv * g2[ch];
            sA2[ch] = A;
            sB2[ch] = bb2[ch] - mean * A;
        }
    }
    float4 acc[4];
    {
        const float4* b4 = (const float4*)&bias[o0];
#pragma unroll
        for (int p = 0; p < 4; p++) acc[p] = b4[p];
    }
    for (int i0 = 0; i0 < H2; i0 += 4) {
        __syncthreads();
        for (int e = tid; e < 1088; e += 256) {
            int ii = e / 272; int rem = e % 272;
            int tr = rem >> 3, wl = rem & 7;
            int tg = t0 - 1 + tr;
            float v = 0.f;
            if (tg >= 0 && tg < 256)
                v = fmaxf(d_F[(i0 + ii) * JTOT + b * 2048 + tg * 8 + wl] * sA2[i0 + ii] + sB2[i0 + ii], 0.f);
            fs[ii][tr][1 + wl] = v;
        }
        for (int e = tid; e < 272; e += 256) {
            int ii = e / 68, rem = e % 68;
            int tr = rem >> 1, side = rem & 1;
            fs[ii][tr][side * 9] = 0.f;
        }
        for (int e = tid; e < 576; e += 256) {
            int o = e & 15, rem = e >> 4;
            int kk = rem % 9, ii = rem / 9;
            ws[ii][kk][o] = w[(o0 + o) * (H2 * 9) + (i0 + ii) * 9 + kk];
        }
        __syncthreads();
#pragma unroll
        for (int ii = 0; ii < 4; ii++) {
            float f[9];
#pragma unroll
            for (int dt = 0; dt < 3; dt++)
#pragma unroll
                for (int dw = 0; dw < 3; dw++)
                    f[dt * 3 + dw] = fs[ii][tl + dt][wq + dw];
#pragma unroll
            for (int kk = 0; kk < 9; kk++) {
                float fv = f[kk];
                const float4* w4 = (const float4*)ws[ii][kk];
#pragma unroll
                for (int p = 0; p < 4; p++) {
                    float4 ww = w4[p];
                    ffma2(acc[p].x, acc[p].y, fv, fv, ww.x, ww.y);
                    ffma2(acc[p].z, acc[p].w, fv, fv, ww.z, ww.w);
                }
            }
        }
    }
    int jout = b * 2048 + (t0 + tl) * 8 + wq;
#pragma unroll
    for (int p = 0; p < 4; p++) {
        d_HT2[head][(o0 + p * 4 + 0) * JTOT + jout] = acc[p].x;
        d_HT2[head][(o0 + p * 4 + 1) * JTOT + jout] = acc[p].y;
        d_HT2[head][(o0 + p * 4 + 2) * JTOT + jout] = acc[p].z;
        d_HT2[head][(o0 + p * 4 + 3) * JTOT + jout] = acc[p].w;
    }
#pragma unroll
    for (int p = 0; p < 4; p++) {
        float s  = acc[p].x + acc[p].y + acc[p].z + acc[p].w;
        float sq = acc[p].x * acc[p].x + acc[p].y * acc[p].y
                 + acc[p].z * acc[p].z + acc[p].w * acc[p].w;
        float2 tot = block_reduce2(s, sq);
        if (tid == 0)
            d_ph[head][(b * 32 + (o0 >> 2) + p) * 8 + blockIdx.x] = tot;
    }
}

// ---------------- heads final v2: 64-j blocks, 4-way i-split ----------------
__global__ void __launch_bounds__(256) head_final_kernel(
        const float* __restrict__ ws2, const float* __restrict__ bs2,
        const float* __restrict__ we2, const float* __restrict__ be2,
        const float* __restrict__ gs, const float* __restrict__ bsn,
        const float* __restrict__ ge, const float* __restrict__ ben,
        float* __restrict__ out) {
    int head = blockIdx.y;
    const float* w2 = head ? we2 : ws2;
    const float* gamma = head ? ge : gs;
    const float* beta  = head ? ben : bsn;
    int b = blockIdx.x >> 5;              // 64 blocks per grid.x: j0 = bx*64
    int j0 = blockIdx.x * 64;
    int tid = threadIdx.x;
    int jl = tid & 63, iq = tid >> 6;     // i-quarter
    __shared__ float sAh[128], sBh[128];
    __shared__ float spart[4][64];
    {
        int g = tid >> 3, c = tid & 7;
        float2 part = d_ph[head][(b * 32 + g) * 8 + c];
        float2 tot = shfl8_reduce2(part);
        float mean = tot.x / 8192.f;
        float var  = tot.y / 8192.f - mean * mean;
        float inv  = rsqrtf(var + 1e-5f);
        if (c < 4) {
            int ch = g * 4 + c;
            float A = inv * gamma[ch];
            sAh[ch] = A;
            sBh[ch] = beta[ch] - mean * A;
        }
    }
    __syncthreads();
    const float* data = d_HT2[head];
    int j = j0 + jl;
    float part = 0.f;
    for (int i = iq * 32; i < iq * 32 + 32; i++) {
        float dv = fmaxf(data[i * JTOT + j] * sAh[i] + sBh[i], 0.f);
        part += w2[i] * dv;
    }
    spart[iq][jl] = part;
    __syncthreads();
    if (iq == 0) {
        float acc = (head ? be2[0] : bs2[0])
                  + spart[0][jl] + spart[1][jl] + spart[2][jl] + spart[3][jl];
        float sg = 1.f / (1.f + expf(-acc));
        int rem = j & 2047;
        out[((b * 2 + head) << 11) + rem] = sg;
    }
}

// ---------------- launch ----------------
extern "C" void kernel_launch(void* const* d_in, const int* in_sizes, int n_in,
                              void* d_out, int out_size) {
    const float* x     = (const float*)d_in[0];
    const float* mask  = (const float*)d_in[1];
    const float* c1_w  = (const float*)d_in[2];
    const float* c1_b  = (const float*)d_in[3];
    const float* gn1_g = (const float*)d_in[4];
    const float* gn1_b = (const float*)d_in[5];
    const float* r3d_w = (const float*)d_in[6];
    const float* r3d_b = (const float*)d_in[7];
    const float* gn3_g = (const float*)d_in[8];
    const float* gn3_b = (const float*)d_in[9];
    const float* r2d_w = (const float*)d_in[10];
    const float* r2d_b = (const float*)d_in[11];
    const float* gn2_g = (const float*)d_in[12];
    const float* gn2_b = (const float*)d_in[13];
    const float* s1_w  = (const float*)d_in[14];
    const float* s1_b  = (const float*)d_in[15];
    const float* sgn_g = (const float*)d_in[16];
    const float* sgn_b = (const float*)d_in[17];
    const float* s2_w  = (const float*)d_in[18];
    const float* s2_b  = (const float*)d_in[19];
    const float* e1_w  = (const float*)d_in[20];
    const float* e1_b  = (const float*)d_in[21];
    const float* egn_g = (const float*)d_in[22];
    const float* egn_b = (const float*)d_in[23];
    const float* e2_w  = (const float*)d_in[24];
    const float* e2_b  = (const float*)d_in[25];
    float* out = (float*)d_out;

    static bool attr_set = false;
    const int gemm_smem = STAGES * (AS_STRIDE + BS_STRIDE) * (int)sizeof(float);
    if (!attr_set) {
        cudaFuncSetAttribute(u_gemm_kernel,
                             cudaFuncAttributeMaxDynamicSharedMemorySize, gemm_smem);
        attr_set = true;
    }

    // 1) conv1+GN1 | W transpose | mask scan
    prep_kernel<<<64 + 4096 + 256, 256>>>(x, c1_w, c1_b, gn1_g, gn1_b, r3d_w, mask);
    // 2) U-GEMM
    u_gemm_kernel<<<dim3(4, 128), 256, gemm_smem>>>();
    // 3) stage2 + GN3 partials
    stage2_kernel<<<dim3(32, 8, 2), 256>>>(r3d_b);
    // 4) r2d v3 (combine3 + apply + GN2 partials)
    r2d_kernel<<<dim3(128, 4), 256>>>(r2d_w, r2d_b, gn3_g, gn3_b);
    // 5) heads conv (combine2 + apply + GN-heads partials)
    head_conv3_kernel<<<dim3(8, 8, 4), 256>>>(s1_w, s1_b, e1_w, e1_b, gn2_g, gn2_b);
    // 6) heads final v2 (combine_h + apply + sigmoid)
    head_final_kernel<<<dim3(64, 2), 256>>>(s2_w, s2_b, e2_w, e2_b,
                                            sgn_g, sgn_b, egn_g, egn_b, out);
}

// round 17
// speedup vs baseline: 1.0243x; 1.0243x over previous
#include <cuda_runtime.h>
#include <mma.h>
using namespace nvcuda;

#define TSCALE 256
#define NS 32
#define NW 8
#define NTW 65536
#define JTOT 4096
#define DIMX 512
#define H1 256
#define H3 512
#define H2 128
#define UCOLS 16384

// ---------------- scratch ----------------
__device__ float d_hT[2 * TSCALE * H1];
__device__ float d_WT[H1 * UCOLS];
__device__ float d_U[(size_t)512 * UCOLS];
__device__ int   d_midx[NTW * 8];
__device__ float d_mval[NTW * 8];
__device__ float d_Y[(size_t)JTOT * H3];        // stage2 output (bias included)
__device__ float d_F[H2 * JTOT];                // raw r2d output
__device__ float d_HT2[2][H2 * JTOT];           // raw head conv outputs
__device__ float2 d_p3[2 * 32 * 256];           // GN3 partials
__device__ float2 d_p2[2 * 32 * 64];            // GN2 partials (64 j-tile chunks)
__device__ float2 d_ph[2][2 * 32 * 8];          // GN-heads partials

// ---------------- packed f32x2 FMA ----------------
__device__ __forceinline__ void ffma2(float& d0, float& d1,
                                      float a0, float a1,
                                      float b0, float b1) {
    asm("{\n\t"
        ".reg .b64 ra, rb, rc;\n\t"
        "mov.b64 ra, {%2, %3};\n\t"
        "mov.b64 rb, {%4, %5};\n\t"
        "mov.b64 rc, {%0, %1};\n\t"
        "fma.rn.f32x2 rc, ra, rb, rc;\n\t"
        "mov.b64 {%0, %1}, rc;\n\t"
        "}"
        : "+f"(d0), "+f"(d1)
        : "f"(a0), "f"(a1), "f"(b0), "f"(b1));
}

// ---------------- deterministic block tree-reduce of (sum,sumsq) ----------------
__device__ __forceinline__ float2 block_reduce2(float s, float sq) {
    __shared__ float sh[512];
    int tid = threadIdx.x;
    __syncthreads();
    sh[tid] = s; sh[256 + tid] = sq;
    __syncthreads();
    for (int st = 128; st > 0; st >>= 1) {
        if (tid < st) { sh[tid] += sh[tid + st]; sh[256 + tid] += sh[256 + tid + st]; }
        __syncthreads();
    }
    return make_float2(sh[0], sh[256]);
}

// 8-lane shuffle reduce of float2
__device__ __forceinline__ float2 shfl8_reduce2(float2 v) {
    v.x += __shfl_xor_sync(~0u, v.x, 1); v.y += __shfl_xor_sync(~0u, v.y, 1);
    v.x += __shfl_xor_sync(~0u, v.x, 2); v.y += __shfl_xor_sync(~0u, v.y, 2);
    v.x += __shfl_xor_sync(~0u, v.x, 4); v.y += __shfl_xor_sync(~0u, v.y, 4);
    return v;
}

// full-warp shuffle reduce of float2
__device__ __forceinline__ float2 shfl32_reduce2(float2 v) {
    v.x += __shfl_xor_sync(~0u, v.x, 1);  v.y += __shfl_xor_sync(~0u, v.y, 1);
    v.x += __shfl_xor_sync(~0u, v.x, 2);  v.y += __shfl_xor_sync(~0u, v.y, 2);
    v.x += __shfl_xor_sync(~0u, v.x, 4);  v.y += __shfl_xor_sync(~0u, v.y, 4);
    v.x += __shfl_xor_sync(~0u, v.x, 8);  v.y += __shfl_xor_sync(~0u, v.y, 8);
    v.x += __shfl_xor_sync(~0u, v.x, 16); v.y += __shfl_xor_sync(~0u, v.y, 16);
    return v;
}

// ---------------- prep: conv1+GN1 | W transpose | mask scan (grid-split) ----------------
__global__ void __launch_bounds__(256) prep_kernel(const float* __restrict__ x,
                                                   const float* __restrict__ cw,
                                                   const float* __restrict__ cbias,
                                                   const float* __restrict__ gamma,
                                                   const float* __restrict__ beta,
                                                   const float* __restrict__ rw,
                                                   const float* __restrict__ mask) {
    int bid = blockIdx.x;
    if (bid < 64) {
        int g = bid & 31, b = bid >> 5;
        int c0 = g * 8;
        int t = threadIdx.x;
        __shared__ float xs[8][TSCALE + 2];
        __shared__ float ws[8][8][3];
        float acc[8];
#pragma unroll
        for (int u = 0; u < 8; u++) acc[u] = cbias[c0 + u];
        for (int i0 = 0; i0 < DIMX; i0 += 8) {
#pragma unroll
            for (int r = 0; r < 8; r++)
                xs[r][t + 1] = x[(b * DIMX + i0 + r) * TSCALE + t];
            if (t < 8) { xs[t][0] = 0.f; xs[t][TSCALE + 1] = 0.f; }
            if (t < 192) {
                int u = t / 24, rem = t % 24, r = rem / 3, k = rem % 3;
                ws[u][r][k] = cw[(c0 + u) * (DIMX * 3) + (i0 + r) * 3 + k];
            }
            __syncthreads();
#pragma unroll
            for (int r = 0; r < 8; r++) {
                float xm = xs[r][t], x0 = xs[r][t + 1], xp = xs[r][t + 2];
#pragma unroll
                for (int u = 0; u < 8; u++)
                    acc[u] += xm * ws[u][r][0] + x0 * ws[u][r][1] + xp * ws[u][r][2];
            }
            __syncthreads();
        }
        float s = 0.f, sq = 0.f;
#pragma unroll
        for (int u = 0; u < 8; u++) { s += acc[u]; sq += acc[u] * acc[u]; }
        float2 tot = block_reduce2(s, sq);
        float mean = tot.x / 2048.f;
        float var  = tot.y / 2048.f - mean * mean;
        float inv  = rsqrtf(var + 1e-5f);
        float v[8];
#pragma unroll
        for (int u = 0; u < 8; u++)
            v[u] = fmaxf((acc[u] - mean) * inv * gamma[c0 + u] + beta[c0 + u], 0.f);
        float* dst = &d_hT[(b * 256 + t) * 256 + c0];
        *(float4*)dst       = make_float4(v[0], v[1], v[2], v[3]);
        *(float4*)(dst + 4) = make_float4(v[4], v[5], v[6], v[7]);
    } else if (bid < 64 + 4096) {
        int q = bid - 64;
        int c  = q & 255;
        int o0 = (q >> 8) * 32;
        __shared__ float tile[32][33];
        int tid = threadIdx.x;
#pragma unroll
        for (int l = 0; l < 4; l++) {
            int e = tid + l * 256;
            int i = e >> 5, n = e & 31;
            tile[i][n] = rw[(size_t)(o0 + i) * 8192 + c * 32 + n];
        }
        __syncthreads();
#pragma unroll
        for (int l = 0; l < 4; l++) {
            int e = tid + l * 256;
            int n = e >> 5, i = e & 31;
            d_WT[(size_t)c * UCOLS + n * 512 + o0 + i] = tile[i][n];
        }
    } else {
        int j = (bid - 64 - 4096) * 256 + threadIdx.x;
        int n = j >> 11, t = (j >> 3) & 255, w = j & 7;
        const float WS[8] = {5.f, 10.f, 20.f, 40.f, 80.f, 160.f, 240.f, 320.f};
        float ws = WS[w];
        float dd = ws * 0.5f;
        float step = ws / 95.f;
        float s0 = (float)t - dd + step * (float)(3 * n);
        float s2 = (float)t - dd + step * (float)(3 * n + 2);
        int lo = max(0, (int)floorf(s0) - 1);
        int hi = min(255, (int)ceilf(s2) + 1);
        int idxs[8]; float vals[8];
        int cnt = 0;
        for (int tin = lo; tin <= hi; tin++) {
            float v = mask[(size_t)tin * NTW + j];
            if (v != 0.f && cnt < 8) { idxs[cnt] = tin; vals[cnt] = v; cnt++; }
        }
#pragma unroll
        for (int s = 0; s < 8; s++) {
            d_midx[j * 8 + s] = (s < cnt) ? idxs[s] : 0;
            d_mval[j * 8 + s] = (s < cnt) ? vals[s] : 0.f;
        }
    }
}

// ---------------- U-GEMM ----------------
#define BM 128
#define BN 128
#define BK 32
#define STAGES 2
#define AS_STRIDE (BM * 36)
#define BS_STRIDE (BK * 132)
#define NKT (H1 / BK)

__device__ __forceinline__ void cp16(void* sdst, const void* gsrc) {
    unsigned saddr = (unsigned)__cvta_generic_to_shared(sdst);
    asm volatile("cp.async.cg.shared.global [%0], [%1], 16;\n"
                 :: "r"(saddr), "l"(gsrc));
}

__global__ void __launch_bounds__(256, 2) u_gemm_kernel() {
    extern __shared__ float smem[];
    float* As = smem;
    float* Bs = smem + STAGES * AS_STRIDE;
    int m0 = blockIdx.x * BM;
    int n0 = blockIdx.y * BN;
    int tid = threadIdx.x;
    int warp = tid >> 5;
    int wm = warp & 1, wn = warp >> 1;

    wmma::fragment<wmma::accumulator, 16, 16, 8, float> acc[4][2];
#pragma unroll
    for (int i = 0; i < 4; i++)
#pragma unroll
        for (int j = 0; j < 2; j++) wmma::fill_fragment(acc[i][j], 0.f);

    auto issue = [&](int s, int kt) {
        int k0 = kt * BK;
        float* as = As + s * AS_STRIDE;
#pragma unroll
        for (int l = 0; l < 4; l++) {
            int q = tid + l * 256;
            int r = q >> 3, c = (q & 7) << 2;
            cp16(as + r * 36 + c, d_hT + (size_t)(m0 + r) * H1 + k0 + c);
        }
        float* bs = Bs + s * BS_STRIDE;
#pragma unroll
        for (int l = 0; l < 4; l++) {
            int q = tid + l * 256;
            int r = q >> 5, c = (q & 31) << 2;
            cp16(bs + r * 132 + c, d_WT + (size_t)(k0 + r) * UCOLS + n0 + c);
        }
        asm volatile("cp.async.commit_group;\n");
    };

    issue(0, 0);
    for (int kt = 0; kt < NKT; kt++) {
        if (kt + 1 < NKT) {
            issue((kt + 1) & 1, kt + 1);
            asm volatile("cp.async.wait_group 1;\n");
        } else {
            asm volatile("cp.async.wait_group 0;\n");
        }
        __syncthreads();
        int s = kt & 1;
        float* as = As + s * AS_STRIDE;
        float* bs = Bs + s * BS_STRIDE;
#pragma unroll
        for (int kk = 0; kk < BK; kk += 8) {
            wmma::fragment<wmma::matrix_a, 16, 16, 8, wmma::precision::tf32, wmma::row_major> af[4];
            wmma::fragment<wmma::matrix_b, 16, 16, 8, wmma::precision::tf32, wmma::row_major> bf[2];
#pragma unroll
            for (int i = 0; i < 4; i++)
                wmma::load_matrix_sync(af[i], as + (wm * 64 + i * 16) * 36 + kk, 36);
#pragma unroll
            for (int j = 0; j < 2; j++)
                wmma::load_matrix_sync(bf[j], bs + kk * 132 + wn * 32 + j * 16, 132);
#pragma unroll
            for (int i = 0; i < 4; i++)
#pragma unroll
                for (int j = 0; j < 2; j++)
                    wmma::mma_sync(acc[i][j], af[i], bf[j], acc[i][j]);
        }
        __syncthreads();
    }
#pragma unroll
    for (int i = 0; i < 4; i++)
#pragma unroll
        for (int j = 0; j < 2; j++)
            wmma::store_matrix_sync(d_U + (size_t)(m0 + wm * 64 + i * 16) * UCOLS + n0 + wn * 32 + j * 16,
                                    acc[i][j], UCOLS, wmma::mem_row_major);
}

// ---------------- stage2 (+ bias + fused GN3 partials) ----------------
__global__ void __launch_bounds__(256) stage2_kernel(const float* __restrict__ bias3) {
    int t0 = blockIdx.x * 8;
    int w  = blockIdx.y;
    int b  = blockIdx.z;
    int tid  = threadIdx.x;
    int lane = tid & 31;
    int wid  = tid >> 5;

    __shared__ int   sidx[NS][8][8];
    __shared__ float sval[NS][8][8];
#pragma unroll
    for (int l = 0; l < 8; l++) {
        int e = tid + l * 256;
        int n = e >> 6, rem = e & 63;
        int tl = rem >> 3, s = rem & 7;
        int j = n * 2048 + (t0 + tl) * 8 + w;
        sidx[n][tl][s] = d_midx[j * 8 + s];
        sval[n][tl][s] = d_mval[j * 8 + s];
    }
    __syncthreads();

    float4 acc[4];
#pragma unroll
    for (int p = 0; p < 4; p++) acc[p] = make_float4(0.f, 0.f, 0.f, 0.f);

    const float4* __restrict__ U4 = (const float4*)d_U;
    for (int n = 0; n < NS; n++) {
#pragma unroll
        for (int s = 0; s < 6; s++) {
            float v = sval[n][wid][s];
            if (v != 0.f) {
                int tin = sidx[n][wid][s];
                size_t base4 = (size_t)(b * 256 + tin) * 4096 + n * 128 + lane;
#pragma unroll
                for (int p = 0; p < 4; p++) {
                    float4 u = U4[base4 + p * 32];
                    ffma2(acc[p].x, acc[p].y, v, v, u.x, u.y);
                    ffma2(acc[p].z, acc[p].w, v, v, u.z, u.w);
                }
            }
        }
    }
    float2 gsum[4];
#pragma unroll
    for (int p = 0; p < 4; p++) {
        float4 bb = ((const float4*)bias3)[p * 32 + lane];
        acc[p].x += bb.x; acc[p].y += bb.y; acc[p].z += bb.z; acc[p].w += bb.w;
        float s  = acc[p].x + acc[p].y + acc[p].z + acc[p].w;
        float sq = acc[p].x * acc[p].x + acc[p].y * acc[p].y
                 + acc[p].z * acc[p].z + acc[p].w * acc[p].w;
        s  += __shfl_xor_sync(~0u, s, 1);  sq += __shfl_xor_sync(~0u, sq, 1);
        s  += __shfl_xor_sync(~0u, s, 2);  sq += __shfl_xor_sync(~0u, sq, 2);
        gsum[p] = make_float2(s, sq);
    }
    float4* Y4 = (float4*)d_Y;
    int t = t0 + wid;
    size_t ob = (size_t)(b * 2048 + t * 8 + w) * 128 + lane;
#pragma unroll
    for (int p = 0; p < 4; p++) Y4[ob + p * 32] = acc[p];

    __shared__ float2 sred[8][32];
    if ((lane & 3) == 0) {
#pragma unroll
        for (int p = 0; p < 4; p++)
            sred[wid][p * 8 + (lane >> 2)] = gsum[p];
    }
    __syncthreads();
    if (tid < 32) {
        float2 tot = make_float2(0.f, 0.f);
#pragma unroll
        for (int ww = 0; ww < 8; ww++) { tot.x += sred[ww][tid].x; tot.y += sred[ww][tid].y; }
        int chunk = blockIdx.x * 8 + w;
        d_p3[(b * 32 + tid) * 256 + chunk] = tot;
    }
}

// ---------------- r2d v2 (measured best): h-tile 64, 256 blocks ----------------
// grid (128 j-tiles of 32, 2 h-tiles of 64); threads 256 = (jl 32, warp hg 8 of 8 h)
__global__ void __launch_bounds__(256) r2d_kernel(const float* __restrict__ w2,
                                                  const float* __restrict__ b2,
                                                  const float* __restrict__ gamma3,
                                                  const float* __restrict__ beta3) {
    int bx = blockIdx.x;
    int j0 = bx * 32;
    int b  = bx >> 6;
    int h0 = blockIdx.y * 64;
    int tid = threadIdx.x;
    int jl = tid & 31, hg = tid >> 5;

    __shared__ float sA[512], sB[512];
    __shared__ float ytile[32][65];
    __shared__ __align__(16) float wst[64][68];

    // combine3 redundantly
    {
        int g = tid >> 3, sl = tid & 7;
        float2 part = make_float2(0.f, 0.f);
        const float2* pp = &d_p3[(b * 32 + g) * 256 + sl * 32];
#pragma unroll 8
        for (int k = 0; k < 32; k++) { float2 p = pp[k]; part.x += p.x; part.y += p.y; }
        float2 tot = shfl8_reduce2(part);
        float mean = tot.x / 32768.f;
        float var  = tot.y / 32768.f - mean * mean;
        float inv  = rsqrtf(var + 1e-5f);
#pragma unroll
        for (int q = 0; q < 2; q++) {
            int o = g * 16 + sl * 2 + q;
            float A = inv * gamma3[o];
            sA[o] = A;
            sB[o] = beta3[o] - mean * A;
        }
    }

    float acc[8];
#pragma unroll
    for (int u = 0; u < 8; u++) acc[u] = b2[h0 + hg * 8 + u];
    __syncthreads();

    const float4* __restrict__ Y4 = (const float4*)d_Y;
    for (int oc = 0; oc < 512; oc += 64) {
        __syncthreads();
#pragma unroll
        for (int l = 0; l < 2; l++) {
            int e = tid + l * 256;
            int row = e >> 4, o4 = e & 15;
            float4 y = Y4[(size_t)(j0 + row) * 128 + (oc >> 2) + o4];
            int ob = oc + o4 * 4;
            ytile[row][o4 * 4 + 0] = fmaxf(y.x * sA[ob + 0] + sB[ob + 0], 0.f);
            ytile[row][o4 * 4 + 1] = fmaxf(y.y * sA[ob + 1] + sB[ob + 1], 0.f);
            ytile[row][o4 * 4 + 2] = fmaxf(y.z * sA[ob + 2] + sB[ob + 2], 0.f);
            ytile[row][o4 * 4 + 3] = fmaxf(y.w * sA[ob + 3] + sB[ob + 3], 0.f);
        }
#pragma unroll
        for (int l = 0; l < 16; l++) {
            int e = tid + l * 256;
            int h = e >> 6, o = e & 63;
            wst[o][h] = w2[(size_t)(h0 + h) * 512 + oc + o];
        }
        __syncthreads();
#pragma unroll 4
        for (int o = 0; o < 64; o++) {
            float yv = ytile[jl][o];
            const float4* wv = (const float4*)&wst[o][hg * 8];
            float4 w0 = wv[0], w1 = wv[1];
            ffma2(acc[0], acc[1], yv, yv, w0.x, w0.y);
            ffma2(acc[2], acc[3], yv, yv, w0.z, w0.w);
            ffma2(acc[4], acc[5], yv, yv, w1.x, w1.y);
            ffma2(acc[6], acc[7], yv, yv, w1.z, w1.w);
        }
    }
    int j = j0 + jl;
#pragma unroll
    for (int u = 0; u < 8; u++)
        d_F[(h0 + hg * 8 + u) * JTOT + j] = acc[u];

    // GN2 partials: warp hg covers 2 groups of 4 h; lanes = j
#pragma unroll
    for (int p = 0; p < 2; p++) {
        float s  = acc[p * 4] + acc[p * 4 + 1] + acc[p * 4 + 2] + acc[p * 4 + 3];
        float sq = acc[p * 4] * acc[p * 4] + acc[p * 4 + 1] * acc[p * 4 + 1]
                 + acc[p * 4 + 2] * acc[p * 4 + 2] + acc[p * 4 + 3] * acc[p * 4 + 3];
        float2 tot = shfl32_reduce2(make_float2(s, sq));
        if (jl == 0) {
            int g = (h0 >> 2) + hg * 2 + p;
            d_p2[(b * 32 + g) * 64 + (bx & 63)] = tot;
        }
    }
}

// ---------------- heads conv3x3 (combine2 + GN2 apply + GN-heads partials fused) ------
__global__ void __launch_bounds__(256) head_conv3_kernel(const float* __restrict__ ws_,
                                                         const float* __restrict__ bs_,
                                                         const float* __restrict__ we_,
                                                         const float* __restrict__ be_,
                                                         const float* __restrict__ g2,
                                                         const float* __restrict__ bb2) {
    int t0 = blockIdx.x * 32;
    int o0 = blockIdx.y * 16;
    int head = blockIdx.z >> 1, b = blockIdx.z & 1;
    const float* w    = head ? we_ : ws_;
    const float* bias = head ? be_ : bs_;
    int tid = threadIdx.x;
    int tl = tid >> 3, wq = tid & 7;
    __shared__ float fs[4][34][10];
    __shared__ __align__(16) float ws[4][9][16];
    __shared__ float sA2[128], sB2[128];
    {
        int g = tid >> 3, sl = tid & 7;
        float2 part = make_float2(0.f, 0.f);
        const float2* pp = &d_p2[(b * 32 + g) * 64 + sl * 8];
#pragma unroll 8
        for (int k = 0; k < 8; k++) { float2 p = pp[k]; part.x += p.x; part.y += p.y; }
        float2 tot = shfl8_reduce2(part);
        float mean = tot.x / 8192.f;
        float var  = tot.y / 8192.f - mean * mean;
        float inv  = rsqrtf(var + 1e-5f);
        if (sl < 4) {
            int ch = g * 4 + sl;
            float A = inv * g2[ch];
            sA2[ch] = A;
            sB2[ch] = bb2[ch] - mean * A;
        }
    }
    float4 acc[4];
    {
        const float4* b4 = (const float4*)&bias[o0];
#pragma unroll
        for (int p = 0; p < 4; p++) acc[p] = b4[p];
    }
    for (int i0 = 0; i0 < H2; i0 += 4) {
        __syncthreads();
        for (int e = tid; e < 1088; e += 256) {
            int ii = e / 272; int rem = e % 272;
            int tr = rem >> 3, wl = rem & 7;
            int tg = t0 - 1 + tr;
            float v = 0.f;
            if (tg >= 0 && tg < 256)
                v = fmaxf(d_F[(i0 + ii) * JTOT + b * 2048 + tg * 8 + wl] * sA2[i0 + ii] + sB2[i0 + ii], 0.f);
            fs[ii][tr][1 + wl] = v;
        }
        for (int e = tid; e < 272; e += 256) {
            int ii = e / 68, rem = e % 68;
            int tr = rem >> 1, side = rem & 1;
            fs[ii][tr][side * 9] = 0.f;
        }
        for (int e = tid; e < 576; e += 256) {
            int o = e & 15, rem = e >> 4;
            int kk = rem % 9, ii = rem / 9;
            ws[ii][kk][o] = w[(o0 + o) * (H2 * 9) + (i0 + ii) * 9 + kk];
        }
        __syncthreads();
#pragma unroll
        for (int ii = 0; ii < 4; ii++) {
            float f[9];
#pragma unroll
            for (int dt = 0; dt < 3; dt++)
#pragma unroll
                for (int dw = 0; dw < 3; dw++)
                    f[dt * 3 + dw] = fs[ii][tl + dt][wq + dw];
#pragma unroll
            for (int kk = 0; kk < 9; kk++) {
                float fv = f[kk];
                const float4* w4 = (const float4*)ws[ii][kk];
#pragma unroll
                for (int p = 0; p < 4; p++) {
                    float4 ww = w4[p];
                    ffma2(acc[p].x, acc[p].y, fv, fv, ww.x, ww.y);
                    ffma2(acc[p].z, acc[p].w, fv, fv, ww.z, ww.w);
                }
            }
        }
    }
    int jout = b * 2048 + (t0 + tl) * 8 + wq;
#pragma unroll
    for (int p = 0; p < 4; p++) {
        d_HT2[head][(o0 + p * 4 + 0) * JTOT + jout] = acc[p].x;
        d_HT2[head][(o0 + p * 4 + 1) * JTOT + jout] = acc[p].y;
        d_HT2[head][(o0 + p * 4 + 2) * JTOT + jout] = acc[p].z;
        d_HT2[head][(o0 + p * 4 + 3) * JTOT + jout] = acc[p].w;
    }
#pragma unroll
    for (int p = 0; p < 4; p++) {
        float s  = acc[p].x + acc[p].y + acc[p].z + acc[p].w;
        float sq = acc[p].x * acc[p].x + acc[p].y * acc[p].y
                 + acc[p].z * acc[p].z + acc[p].w * acc[p].w;
        float2 tot = block_reduce2(s, sq);
        if (tid == 0)
            d_ph[head][(b * 32 + (o0 >> 2) + p) * 8 + blockIdx.x] = tot;
    }
}

// ---------------- heads final v2: 64-j blocks, 4-way i-split ----------------
__global__ void __launch_bounds__(256) head_final_kernel(
        const float* __restrict__ ws2, const float* __restrict__ bs2,
        const float* __restrict__ we2, const float* __restrict__ be2,
        const float* __restrict__ gs, const float* __restrict__ bsn,
        const float* __restrict__ ge, const float* __restrict__ ben,
        float* __restrict__ out) {
    int head = blockIdx.y;
    const float* w2 = head ? we2 : ws2;
    const float* gamma = head ? ge : gs;
    const float* beta  = head ? ben : bsn;
    int b = blockIdx.x >> 5;
    int j0 = blockIdx.x * 64;
    int tid = threadIdx.x;
    int jl = tid & 63, iq = tid >> 6;
    __shared__ float sAh[128], sBh[128];
    __shared__ float spart[4][64];
    {
        int g = tid >> 3, c = tid & 7;
        float2 part = d_ph[head][(b * 32 + g) * 8 + c];
        float2 tot = shfl8_reduce2(part);
        float mean = tot.x / 8192.f;
        float var  = tot.y / 8192.f - mean * mean;
        float inv  = rsqrtf(var + 1e-5f);
        if (c < 4) {
            int ch = g * 4 + c;
            float A = inv * gamma[ch];
            sAh[ch] = A;
            sBh[ch] = beta[ch] - mean * A;
        }
    }
    __syncthreads();
    const float* data = d_HT2[head];
    int j = j0 + jl;
    float part = 0.f;
    for (int i = iq * 32; i < iq * 32 + 32; i++) {
        float dv = fmaxf(data[i * JTOT + j] * sAh[i] + sBh[i], 0.f);
        part += w2[i] * dv;
    }
    spart[iq][jl] = part;
    __syncthreads();
    if (iq == 0) {
        float acc = (head ? be2[0] : bs2[0])
                  + spart[0][jl] + spart[1][jl] + spart[2][jl] + spart[3][jl];
        float sg = 1.f / (1.f + expf(-acc));
        int rem = j & 2047;
        out[((b * 2 + head) << 11) + rem] = sg;
    }
}

// ---------------- launch ----------------
extern "C" void kernel_launch(void* const* d_in, const int* in_sizes, int n_in,
                              void* d_out, int out_size) {
    const float* x     = (const float*)d_in[0];
    const float* mask  = (const float*)d_in[1];
    const float* c1_w  = (const float*)d_in[2];
    const float* c1_b  = (const float*)d_in[3];
    const float* gn1_g = (const float*)d_in[4];
    const float* gn1_b = (const float*)d_in[5];
    const float* r3d_w = (const float*)d_in[6];
    const float* r3d_b = (const float*)d_in[7];
    const float* gn3_g = (const float*)d_in[8];
    const float* gn3_b = (const float*)d_in[9];
    const float* r2d_w = (const float*)d_in[10];
    const float* r2d_b = (const float*)d_in[11];
    const float* gn2_g = (const float*)d_in[12];
    const float* gn2_b = (const float*)d_in[13];
    const float* s1_w  = (const float*)d_in[14];
    const float* s1_b  = (const float*)d_in[15];
    const float* sgn_g = (const float*)d_in[16];
    const float* sgn_b = (const float*)d_in[17];
    const float* s2_w  = (const float*)d_in[18];
    const float* s2_b  = (const float*)d_in[19];
    const float* e1_w  = (const float*)d_in[20];
    const float* e1_b  = (const float*)d_in[21];
    const float* egn_g = (const float*)d_in[22];
    const float* egn_b = (const float*)d_in[23];
    const float* e2_w  = (const float*)d_in[24];
    const float* e2_b  = (const float*)d_in[25];
    float* out = (float*)d_out;

    static bool attr_set = false;
    const int gemm_smem = STAGES * (AS_STRIDE + BS_STRIDE) * (int)sizeof(float);
    if (!attr_set) {
        cudaFuncSetAttribute(u_gemm_kernel,
                             cudaFuncAttributeMaxDynamicSharedMemorySize, gemm_smem);
        attr_set = true;
    }

    // 1) conv1+GN1 | W transpose | mask scan
    prep_kernel<<<64 + 4096 + 256, 256>>>(x, c1_w, c1_b, gn1_g, gn1_b, r3d_w, mask);
    // 2) U-GEMM
    u_gemm_kernel<<<dim3(4, 128), 256, gemm_smem>>>();
    // 3) stage2 + GN3 partials
    stage2_kernel<<<dim3(32, 8, 2), 256>>>(r3d_b);
    // 4) r2d v2 (combine3 + apply + GN2 partials)
    r2d_kernel<<<dim3(128, 2), 256>>>(r2d_w, r2d_b, gn3_g, gn3_b);
    // 5) heads conv (combine2 + apply + GN-heads partials)
    head_conv3_kernel<<<dim3(8, 8, 4), 256>>>(s1_w, s1_b, e1_w, e1_b, gn2_g, gn2_b);
    // 6) heads final v2 (combine_h + apply + sigmoid)
    head_final_kernel<<<dim3(64, 2), 256>>>(s2_w, s2_b, e2_w, e2_b,
                                            sgn_g, sgn_b, egn_g, egn_b, out);
}